// round 3
// baseline (speedup 1.0000x reference)
#include <cuda_runtime.h>

#define NN 576
#define MROWS 144
#define ROW_DEG 15
#define BATCH 256
#define ITERS 3
#define MAXCOLDEG 32

// Persistent structure (rebuilt deterministically every launch; no allocs).
__device__ short       g_cols[MROWS * ROW_DEG];   // edge -> column index
__device__ signed char g_pos[MROWS * NN];         // (m,n) -> k within row, or -1
__device__ short       g_col_eid[NN * MAXCOLDEG]; // column -> edge ids (m*15+k)
__device__ int         g_col_deg[NN];

// One warp per check row: ballot-scan the H row, emit column indices + positions.
__global__ void build_rows(const float* __restrict__ H) {
    int m = blockIdx.x;
    int lane = threadIdx.x;
    const float* row = H + m * NN;
    int base = 0;
    for (int c0 = 0; c0 < NN; c0 += 32) {
        float v = row[c0 + lane];
        unsigned act = __ballot_sync(0xffffffffu, v != 0.0f);
        if (v != 0.0f) {
            int k = base + __popc(act & ((1u << lane) - 1u));
            g_cols[m * ROW_DEG + k] = (short)(c0 + lane);
            g_pos[m * NN + c0 + lane] = (signed char)k;
        } else {
            g_pos[m * NN + c0 + lane] = -1;
        }
        base += __popc(act);
    }
}

// One thread per variable column: deterministic ordered edge list (CSC).
__global__ void build_cols(const float* __restrict__ H) {
    int n = blockIdx.x * 32 + threadIdx.x;
    if (n >= NN) return;
    int deg = 0;
    for (int m = 0; m < MROWS; m++) {
        if (H[m * NN + n] != 0.0f) {
            int k = g_pos[m * NN + n];
            if (deg < MAXCOLDEG)
                g_col_eid[n * MAXCOLDEG + deg] = (short)(m * ROW_DEG + k);
            deg++;
        }
    }
    g_col_deg[n] = deg < MAXCOLDEG ? deg : MAXCOLDEG;
}

#define BPB 2                 // batch elements per CTA
#define TPB (BPB * MROWS)     // 288 threads: every thread owns one (batch,row)

__global__ __launch_bounds__(TPB) void decode(
    const float* __restrict__ r,
    const float* __restrict__ alpha,
    const float* __restrict__ beta,
    float* __restrict__ out)
{
    __shared__ float sL[BPB * NN];                 // posterior L = r + colsum(E)
    __shared__ float sR[BPB * NN];                 // cached r
    __shared__ float sE[BPB * MROWS * ROW_DEG];    // edge messages (for column gather)

    const int t = threadIdx.x;
    const int bb = blockIdx.x * BPB;

    // Load r for both batch elements; init L = r.
    for (int i = t; i < BPB * NN; i += TPB) {
        int sub = i / NN, n = i - sub * NN;
        float v = r[(bb + sub) * NN + n];
        sR[i] = v;
        sL[i] = v;
    }

    const int sub = t / MROWS;
    const int m = t - sub * MROWS;

    // Row structure + messages in registers.
    int cols_[ROW_DEG];
#pragma unroll
    for (int k = 0; k < ROW_DEG; k++) cols_[k] = g_cols[m * ROW_DEG + k];
    float E[ROW_DEG];
#pragma unroll
    for (int k = 0; k < ROW_DEG; k++) E[k] = 0.0f;

    float* myL = sL + sub * NN;
    float* myE = sE + (sub * MROWS + m) * ROW_DEG;

    const float a0 = alpha[0], a1 = alpha[1], a2 = alpha[2];
    const float o0 = beta[0],  o1 = beta[1],  o2 = beta[2];

    __syncthreads();

#pragma unroll
    for (int it = 0; it < ITERS; it++) {
        const float a    = (it == 0) ? a0 : (it == 1) ? a1 : a2;
        const float ofs  = (it == 0) ? o0 : (it == 1) ? o1 : o2;

        // --- check-node (row) update: min-sum with offset + alpha scaling ---
        float min1 = 3.4e38f, min2 = 3.4e38f;
        int idx = 0;
        unsigned smask = 0;
#pragma unroll
        for (int k = 0; k < ROW_DEG; k++) {
            float mv = myL[cols_[k]] - E[k];     // extrinsic input M
            float av = fabsf(mv);
            smask |= (__float_as_uint(mv) >> 31) << k;
            if (av < min1) { min2 = min1; min1 = av; idx = k; }
            else if (av < min2) { min2 = av; }
        }
        const float v1 = a * fmaxf(0.0f, min1 - ofs);
        const float v2 = a * fmaxf(0.0f, min2 - ofs);
        const unsigned par = __popc(smask) & 1u;
#pragma unroll
        for (int k = 0; k < ROW_DEG; k++) {
            float mag = (k == idx) ? v2 : v1;
            unsigned neg = par ^ ((smask >> k) & 1u);  // sign product excl. self
            float e = neg ? -mag : mag;
            E[k] = e;
            myE[k] = e;   // stride-15 stores: conflict-free (gcd(15,32)=1)
        }
        __syncthreads();

        // --- variable-node (column) update: L = r + colsum(E), deterministic ---
        for (int i = t; i < BPB * NN; i += TPB) {
            int s2 = i / NN, n = i - s2 * NN;
            float s = sR[i];
            const int deg = g_col_deg[n];
            const short* eid = g_col_eid + n * MAXCOLDEG;
            const float* Eb = sE + s2 * MROWS * ROW_DEG;
            for (int j = 0; j < deg; j++) s += Eb[eid[j]];
            sL[i] = s;
        }
        __syncthreads();
    }

    // Output = r + colsum(E_last) = final L.
    for (int i = t; i < BPB * NN; i += TPB) {
        int s2 = i / NN, n = i - s2 * NN;
        out[(bb + s2) * NN + n] = sL[i];
    }
}

extern "C" void kernel_launch(void* const* d_in, const int* in_sizes, int n_in,
                              void* d_out, int out_size) {
    const float* r     = (const float*)d_in[0];   // [256, 576]
    const float* H     = (const float*)d_in[1];   // [144, 576]
    const float* alpha = (const float*)d_in[2];   // [3]
    const float* beta  = (const float*)d_in[3];   // [3]
    float* out = (float*)d_out;                   // [256, 576]

    build_rows<<<MROWS, 32>>>(H);
    build_cols<<<(NN + 31) / 32, 32>>>(H);
    decode<<<BATCH / BPB, TPB>>>(r, alpha, beta, out);
}

// round 4
// speedup vs baseline: 2.1151x; 2.1151x over previous
#include <cuda_runtime.h>

#define NN 576
#define MROWS 144
#define ROW_DEG 15
#define EDGES (MROWS * ROW_DEG)
#define BATCH 256
#define ITERS 3
#define MAXD 24          // max column degree guard (actual ~11 for Binom(144, 15/576))
#define COLW 5           // ceil(144/32) mask words per column

// Persistent structure (rebuilt deterministically every launch; no allocs).
__device__ short g_cols[EDGES];        // edge (m*15+k) -> column index
__device__ short g_eid_t[MAXD * NN];   // transposed CSC: [j][n] -> edge id
__device__ int   g_deg[NN];            // column degree

// ---------------------------------------------------------------------------
// ONE structure kernel, single CTA of 1024 threads. All intermediates in smem.
// ---------------------------------------------------------------------------
__global__ __launch_bounds__(1024) void build_struct(const float* __restrict__ H) {
    __shared__ unsigned smask[NN * COLW];      // column occupancy bitmasks (11.5KB)
    __shared__ short    scols[EDGES];          // row -> columns (4.3KB)

    const int t = threadIdx.x;
    const int warp = t >> 5, lane = t & 31;

    for (int i = t; i < NN * COLW; i += 1024) smask[i] = 0u;
    __syncthreads();

    // Row scan: warp w handles rows w, w+32, ... Prefetch the whole row first
    // (18 independent LDGs -> one memory latency), then 18 ballot rounds.
    for (int m = warp; m < MROWS; m += 32) {
        const float* row = H + m * NN;
        float v[18];
#pragma unroll
        for (int j = 0; j < 18; j++) v[j] = row[j * 32 + lane];
        int base = 0;
#pragma unroll
        for (int j = 0; j < 18; j++) {
            unsigned act = __ballot_sync(0xffffffffu, v[j] != 0.0f);
            if (v[j] != 0.0f) {
                int k = base + __popc(act & ((1u << lane) - 1u));
                int n = j * 32 + lane;
                scols[m * ROW_DEG + k] = (short)n;
                atomicOr(&smask[n * COLW + (m >> 5)], 1u << (m & 31));
            }
            base += __popc(act);
        }
    }
    __syncthreads();

    for (int i = t; i < EDGES; i += 1024) g_cols[i] = scols[i];

    // CSC build: thread n walks its column's bitmask (deterministic order:
    // ascending m), finds k by searching the 15-entry row list in shared.
    if (t < NN) {
        const int n = t;
        int deg = 0;
#pragma unroll
        for (int w = 0; w < COLW; w++) {
            unsigned b = smask[n * COLW + w];
            while (b) {
                int m = w * 32 + __ffs(b) - 1;
                b &= b - 1;
                int k = 0;
#pragma unroll
                for (int kk = 0; kk < ROW_DEG; kk++)
                    if (scols[m * ROW_DEG + kk] == (short)n) k = kk;
                if (deg < MAXD) g_eid_t[deg * NN + n] = (short)(m * ROW_DEG + k);
                deg++;
            }
        }
        g_deg[n] = deg < MAXD ? deg : MAXD;
    }
}

// ---------------------------------------------------------------------------
// Decoder: 2 batch elements per CTA, 288 threads (one per (batch,row)).
// All structure staged to shared; 3-iteration loop touches shared only.
// ---------------------------------------------------------------------------
#define BPB 2
#define TPB (BPB * MROWS)

__global__ __launch_bounds__(TPB) void decode(
    const float* __restrict__ r,
    const float* __restrict__ alpha,
    const float* __restrict__ beta,
    float* __restrict__ out)
{
    __shared__ float sL[BPB * NN];             // posterior L = r + colsum(E)
    __shared__ float sR[BPB * NN];             // cached r
    __shared__ float sE[BPB * EDGES];          // edge messages (for column gather)
    __shared__ short seid[MAXD * NN];          // staged transposed CSC (27.6KB)
    __shared__ unsigned char sdeg[NN];

    const int t = threadIdx.x;
    const int bb = blockIdx.x * BPB;

    // Stage structure (coalesced, overlapped with r loads).
    for (int i = t; i < (MAXD * NN) / 2; i += TPB)
        ((int*)seid)[i] = ((const int*)g_eid_t)[i];
    for (int i = t; i < NN; i += TPB) sdeg[i] = (unsigned char)g_deg[i];

    for (int i = t; i < BPB * NN; i += TPB) {
        int sub = i / NN, n = i - sub * NN;
        float v = r[(bb + sub) * NN + n];
        sR[i] = v;
        sL[i] = v;
    }

    const int sub = t / MROWS;
    const int m = t - sub * MROWS;

    int cols_[ROW_DEG];
#pragma unroll
    for (int k = 0; k < ROW_DEG; k++) cols_[k] = g_cols[m * ROW_DEG + k];
    float E[ROW_DEG];
#pragma unroll
    for (int k = 0; k < ROW_DEG; k++) E[k] = 0.0f;

    float* myL = sL + sub * NN;
    float* myE = sE + sub * EDGES + m * ROW_DEG;

    const float a0 = alpha[0], a1 = alpha[1], a2 = alpha[2];
    const float o0 = beta[0],  o1 = beta[1],  o2 = beta[2];

    __syncthreads();

#pragma unroll
    for (int it = 0; it < ITERS; it++) {
        const float a   = (it == 0) ? a0 : (it == 1) ? a1 : a2;
        const float ofs = (it == 0) ? o0 : (it == 1) ? o1 : o2;

        // --- check-node (row) update: offset min-sum ---
        float min1 = 3.4e38f, min2 = 3.4e38f;
        int idx = 0;
        unsigned smaskr = 0;
#pragma unroll
        for (int k = 0; k < ROW_DEG; k++) {
            float mv = myL[cols_[k]] - E[k];     // extrinsic input M
            float av = fabsf(mv);
            smaskr |= (__float_as_uint(mv) >> 31) << k;
            if (av < min1) { min2 = min1; min1 = av; idx = k; }
            else if (av < min2) { min2 = av; }
        }
        const float v1 = a * fmaxf(0.0f, min1 - ofs);
        const float v2 = a * fmaxf(0.0f, min2 - ofs);
        const unsigned par = __popc(smaskr) & 1u;
#pragma unroll
        for (int k = 0; k < ROW_DEG; k++) {
            float mag = (k == idx) ? v2 : v1;
            unsigned neg = par ^ ((smaskr >> k) & 1u);
            float e = neg ? -mag : mag;
            E[k] = e;
            myE[k] = e;    // stride-15: gcd(15,32)=1, conflict-light
        }
        __syncthreads();

        // --- variable-node (column) update: L = r + colsum(E), shared only ---
        for (int i = t; i < BPB * NN; i += TPB) {
            int s2 = i / NN, n = i - s2 * NN;
            float s = sR[i];
            const int deg = sdeg[n];
            const float* Eb = sE + s2 * EDGES;
#pragma unroll 4
            for (int j = 0; j < deg; j++) s += Eb[seid[j * NN + n]];
            sL[i] = s;
        }
        __syncthreads();
    }

    for (int i = t; i < BPB * NN; i += TPB) {
        int s2 = i / NN, n = i - s2 * NN;
        out[(bb + s2) * NN + n] = sL[i];
    }
}

extern "C" void kernel_launch(void* const* d_in, const int* in_sizes, int n_in,
                              void* d_out, int out_size) {
    const float* r     = (const float*)d_in[0];   // [256, 576]
    const float* H     = (const float*)d_in[1];   // [144, 576]
    const float* alpha = (const float*)d_in[2];   // [3]
    const float* beta  = (const float*)d_in[3];   // [3]
    float* out = (float*)d_out;                   // [256, 576]

    build_struct<<<1, 1024>>>(H);
    decode<<<BATCH / BPB, TPB>>>(r, alpha, beta, out);
}